// round 11
// baseline (speedup 1.0000x reference)
#include <cuda_runtime.h>
#include <cuda_fp16.h>
#include <cstdint>

#define B_  8
#define T_  200
#define U_  50
#define DE  512
#define DP  640
#define DJ  640
#define V_  1024

#define MT     128                 // M rows per CTA (16 t x 8 u)
#define NTILE  256                 // vocab cols per CTA pass
#define NPASS  (V_ / NTILE)        // 4
#define KSTEPS (DJ / 16)           // 40 k16 steps

#define SA   648   // As stride halves; 324 words, %32=4 -> ldsm conflict-free
#define SAW  324

#define AS_BYTES   (MT * SA * 2)               // 165888
#define ENC_OFF    AS_BYTES
#define PRED_OFF   (ENC_OFF + 16 * 64 * 4)
#define JOINT_SMEM (PRED_OFF + 8 * 64 * 4)     // 172032

// Scratch
__device__ float  g_enc [B_ * T_ * DJ];
__device__ float  g_pred[B_ * U_ * DJ];
// W pre-shuffled into mma B-fragment order:
// uint4 index = (n16 * KSTEPS + kstep) * 32 + lane
__device__ __align__(16) __half g_wh[V_ * DJ];

// ---------------------------------------------------------------------------
__device__ __forceinline__ uint32_t smem_u32(const void* p) {
    return (uint32_t)__cvta_generic_to_shared(p);
}
__device__ __forceinline__ void ldsm_x4(uint32_t& r0, uint32_t& r1, uint32_t& r2,
                                        uint32_t& r3, uint32_t a) {
    asm volatile("ldmatrix.sync.aligned.m8n8.x4.shared.b16 {%0,%1,%2,%3}, [%4];\n"
                 : "=r"(r0), "=r"(r1), "=r"(r2), "=r"(r3) : "r"(a));
}
__device__ __forceinline__ float tanh_fast(float x) {
    float y;
    asm("tanh.approx.f32 %0, %1;" : "=f"(y) : "f"(x));
    return y;
}
__device__ __forceinline__ uint32_t packh2(float a, float b) {
    half2 h = __floats2half2_rn(a, b);
    return *(uint32_t*)&h;
}

// ---------------------------------------------------------------------------
// W_out fp32 -> fp16, shuffled into B-fragment order.
// ---------------------------------------------------------------------------
__global__ __launch_bounds__(256)
void convert_w_kernel(const float* __restrict__ W, uint4* __restrict__ Wh) {
    int tid = blockIdx.x * blockDim.x + threadIdx.x;
    if (tid >= (V_ / 16) * KSTEPS * 32) return;
    int lane = tid & 31;
    int rest = tid >> 5;
    int ks = rest % KSTEPS;
    int n16 = rest / KSTEPS;
    int g = lane >> 2, tg = lane & 3;

    const float* r0p = W + (size_t)(n16 * 16 + g) * DJ + ks * 16 + tg * 2;
    const float* r1p = r0p + 8 * DJ;
    float2 w0 = *(const float2*)(r0p);
    float2 w1 = *(const float2*)(r0p + 8);
    float2 w2 = *(const float2*)(r1p);
    float2 w3 = *(const float2*)(r1p + 8);
    uint4 o;
    o.x = packh2(w0.x, w0.y);
    o.y = packh2(w1.x, w1.y);
    o.z = packh2(w2.x, w2.y);
    o.w = packh2(w3.x, w3.y);
    Wh[tid] = o;
}

// ---------------------------------------------------------------------------
// Merged projection GEMMs: z=0 -> enc, z=1 -> pred. fp32, 32x64 tiles.
// ---------------------------------------------------------------------------
__global__ __launch_bounds__(256)
void proj_kernel(const float* __restrict__ Aenc, const float* __restrict__ Wenc,
                 const float* __restrict__ benc, float* __restrict__ Cenc,
                 const float* __restrict__ Apred, const float* __restrict__ Wpred,
                 const float* __restrict__ bpred, float* __restrict__ Cpred) {
    int z = blockIdx.z;
    const float* A    = z ? Apred : Aenc;
    const float* W    = z ? Wpred : Wenc;
    const float* bias = z ? bpred : benc;
    float*       C    = z ? Cpred : Cenc;
    int M = z ? (B_ * U_) : (B_ * T_);
    int D = z ? DP : DE;

    int m0 = blockIdx.y * 32;
    if (m0 >= M) return;
    int j0 = blockIdx.x * 64;

    __shared__ float As[32][17];
    __shared__ float Ws[64][17];
    int tid = threadIdx.x;
    int tx = tid & 15, ty = tid >> 4;

    float acc[2][4];
    #pragma unroll
    for (int i = 0; i < 2; i++)
        #pragma unroll
        for (int j = 0; j < 4; j++) acc[i][j] = 0.f;

    for (int kt = 0; kt < D; kt += 16) {
        #pragma unroll
        for (int i = 0; i < 2; i++) {
            int idx = tid + i * 256;
            int r = idx >> 4, k = idx & 15;
            int m = m0 + r;
            As[r][k] = (m < M) ? A[(size_t)m * D + kt + k] : 0.f;
        }
        #pragma unroll
        for (int i = 0; i < 4; i++) {
            int idx = tid + i * 256;
            int r = idx >> 4, k = idx & 15;
            Ws[r][k] = W[(size_t)(j0 + r) * D + kt + k];
        }
        __syncthreads();
        #pragma unroll
        for (int kk = 0; kk < 16; kk++) {
            float a0 = As[ty][kk], a1 = As[ty + 16][kk];
            float w[4];
            #pragma unroll
            for (int j = 0; j < 4; j++) w[j] = Ws[tx + j * 16][kk];
            #pragma unroll
            for (int j = 0; j < 4; j++) {
                acc[0][j] += a0 * w[j];
                acc[1][j] += a1 * w[j];
            }
        }
        __syncthreads();
    }
    #pragma unroll
    for (int i = 0; i < 2; i++) {
        int m = m0 + ty + i * 16;
        if (m >= M) continue;
        #pragma unroll
        for (int j = 0; j < 4; j++) {
            int jj = j0 + tx + j * 16;
            C[(size_t)m * DJ + jj] = acc[i][j] + bias[jj];
        }
    }
}

// ---------------------------------------------------------------------------
// Joint kernel: CTA = 128 M-rows (16t x 8u) x V=1024 in 4 passes of N=256.
// 512 threads = 16 warps (4m x 4n), warp tile 32x64, 4 warps/SMSP.
// Phase 2: no barriers, B streamed from L2 in frag order, A via ldsm.
// ---------------------------------------------------------------------------
extern __shared__ __align__(128) char dynsmem[];

__global__ __launch_bounds__(512, 1)
void joint_kernel(const float* __restrict__ bout, float* __restrict__ out) {
    half*  As    = (half*)dynsmem;
    float* encs  = (float*)(dynsmem + ENC_OFF);    // 16 x 64
    float* preds = (float*)(dynsmem + PRED_OFF);   // 8 x 64

    int tid = threadIdx.x;
    int wid = tid >> 5, lane = tid & 31;
    int g = lane >> 2, tg = lane & 3;
    int warp_m = wid >> 2, warp_n = wid & 3;   // 4 x 4

    int bx = blockIdx.x;               // 728 CTAs: 13 t-tiles x 7 u-tiles x 8 b
    int b = bx / 91, r = bx % 91;
    int tt = r % 13, ut = r / 13;
    int t0 = tt * 16, u0 = ut * 8;

    uint32_t as_u = smem_u32(As);

    // ---- Phase 1: A = tanh(enc + pred), fp16, once ----
    const float* encp  = g_enc  + ((size_t)b * T_ + t0) * DJ;
    const float* predp = g_pred + ((size_t)b * U_ + u0) * DJ;
    for (int kc = 0; kc < DJ; kc += 64) {
        {   // enc 16x64: 512 float2, one per thread
            int rw = tid >> 5, kp = tid & 31;
            int t = t0 + rw;
            float2 ev = make_float2(0.f, 0.f);
            if (t < T_) ev = *(const float2*)(encp + (size_t)rw * DJ + kc + kp * 2);
            *(float2*)(encs + rw * 64 + kp * 2) = ev;
        }
        if (tid < 256) {   // pred 8x64: 256 float2
            int rw = tid >> 5, kp = tid & 31;
            int u = u0 + rw;
            float2 pv = make_float2(0.f, 0.f);
            if (u < U_) pv = *(const float2*)(predp + (size_t)rw * DJ + kc + kp * 2);
            *(float2*)(preds + rw * 64 + kp * 2) = pv;
        }
        __syncthreads();
        #pragma unroll
        for (int i = 0; i < 8; i++) {      // 128 rows x 32 half2
            int idx = tid + i * 512;
            int row = idx >> 5, kp = idx & 31;
            float2 e = *(const float2*)(encs + ((row >> 3) << 6) + kp * 2);
            float2 p = *(const float2*)(preds + ((row & 7) << 6) + kp * 2);
            half2 h = __floats2half2_rn(tanh_fast(e.x + p.x), tanh_fast(e.y + p.y));
            *(half2*)(As + row * SA + kc + kp * 2) = h;
        }
        __syncthreads();
    }

    // ---- Phase 2: 4 vocab passes x 40 k16-steps. No barriers. ----
    int j = lane >> 3;
    int a_row = warp_m * 32 + (lane & 7) + (j & 1) * 8;   // + mt*16
    int a_col = (j >> 1) * 4;

    const uint4* wsh = (const uint4*)g_wh;

    for (int np = 0; np < NPASS; np++) {
        float acc[2][8][4];
        #pragma unroll
        for (int mt = 0; mt < 2; mt++)
            #pragma unroll
            for (int nt = 0; nt < 8; nt++)
                #pragma unroll
                for (int c = 0; c < 4; c++) acc[mt][nt][c] = 0.f;

        int n16b = np * (NTILE / 16) + warp_n * 4;
        const uint4* wp0 = wsh + ((size_t)(n16b + 0) * KSTEPS) * 32 + lane;
        const uint4* wp1 = wsh + ((size_t)(n16b + 1) * KSTEPS) * 32 + lane;
        const uint4* wp2 = wsh + ((size_t)(n16b + 2) * KSTEPS) * 32 + lane;
        const uint4* wp3 = wsh + ((size_t)(n16b + 3) * KSTEPS) * 32 + lane;

        for (int ks = 0; ks < KSTEPS; ks++) {
            uint4 bq[4];
            bq[0] = wp0[ks * 32];
            bq[1] = wp1[ks * 32];
            bq[2] = wp2[ks * 32];
            bq[3] = wp3[ks * 32];

            uint32_t a[2][4];
            #pragma unroll
            for (int mt = 0; mt < 2; mt++)
                ldsm_x4(a[mt][0], a[mt][1], a[mt][2], a[mt][3],
                        as_u + (uint32_t)((a_row + mt * 16) * SAW
                                          + ks * 8 + a_col) * 4);
            #pragma unroll
            for (int mt = 0; mt < 2; mt++) {
                #pragma unroll
                for (int nt = 0; nt < 8; nt++) {
                    uint32_t bf0 = (nt & 1) ? bq[nt >> 1].z : bq[nt >> 1].x;
                    uint32_t bf1 = (nt & 1) ? bq[nt >> 1].w : bq[nt >> 1].y;
                    asm volatile(
                        "mma.sync.aligned.m16n8k16.row.col.f32.f16.f16.f32 "
                        "{%0,%1,%2,%3}, {%4,%5,%6,%7}, {%8,%9}, {%0,%1,%2,%3};\n"
                        : "+f"(acc[mt][nt][0]), "+f"(acc[mt][nt][1]),
                          "+f"(acc[mt][nt][2]), "+f"(acc[mt][nt][3])
                        : "r"(a[mt][0]), "r"(a[mt][1]), "r"(a[mt][2]), "r"(a[mt][3]),
                          "r"(bf0), "r"(bf1));
                }
            }
        }

        // epilogue for this pass
        int n0 = np * NTILE;
        #pragma unroll
        for (int nt = 0; nt < 8; nt++) {
            int n = n0 + warp_n * 64 + nt * 8 + tg * 2;
            float bo0 = __ldg(bout + n);
            float bo1 = __ldg(bout + n + 1);
            #pragma unroll
            for (int mt = 0; mt < 2; mt++) {
                #pragma unroll
                for (int h = 0; h < 2; h++) {
                    int row = warp_m * 32 + mt * 16 + g + h * 8;
                    int t = t0 + (row >> 3), u = u0 + (row & 7);
                    if (t < T_ && u < U_) {
                        size_t base = ((((size_t)b * T_ + t) * U_ + u) * V_) + n;
                        float2 v = make_float2(acc[mt][nt][h * 2] + bo0,
                                               acc[mt][nt][h * 2 + 1] + bo1);
                        *(float2*)(out + base) = v;
                    }
                }
            }
        }
    }
}

// ---------------------------------------------------------------------------
extern "C" void kernel_launch(void* const* d_in, const int* in_sizes, int n_in,
                              void* d_out, int out_size) {
    const float* encoder_out   = (const float*)d_in[0];
    const float* predictor_out = (const float*)d_in[1];
    const float* W_enc  = (const float*)d_in[2];
    const float* b_enc  = (const float*)d_in[3];
    const float* W_pred = (const float*)d_in[4];
    const float* b_pred = (const float*)d_in[5];
    const float* W_out  = (const float*)d_in[6];
    const float* b_out  = (const float*)d_in[7];
    float* out = (float*)d_out;

    float* enc_buf;
    float* pred_buf;
    uint4* wh_buf;
    cudaGetSymbolAddress((void**)&enc_buf,  g_enc);
    cudaGetSymbolAddress((void**)&pred_buf, g_pred);
    cudaGetSymbolAddress((void**)&wh_buf,   g_wh);

    cudaFuncSetAttribute(joint_kernel,
                         cudaFuncAttributeMaxDynamicSharedMemorySize, JOINT_SMEM);

    convert_w_kernel<<<((V_ / 16) * KSTEPS * 32 + 255) / 256, 256>>>(W_out, wh_buf);

    {   // merged projections
        dim3 grid(DJ / 64, (B_ * T_ + 31) / 32, 2);
        proj_kernel<<<grid, 256>>>(encoder_out, W_enc, b_enc, enc_buf,
                                   predictor_out, W_pred, b_pred, pred_buf);
    }

    joint_kernel<<<728, 512, JOINT_SMEM>>>(b_out, out);
}

// round 12
// speedup vs baseline: 1.1015x; 1.1015x over previous
#include <cuda_runtime.h>
#include <cuda_fp16.h>
#include <cstdint>

#define B_  8
#define T_  200
#define U_  50
#define DE  512
#define DP  640
#define DJ  640
#define V_  1024

#define MT     64                  // M rows per CTA (8 t x 8 u)
#define NTILE  256                 // vocab cols per CTA pass
#define NPASS  (V_ / NTILE)        // 4
#define KSTEPS (DJ / 16)           // 40 k16 steps

#define SA   648   // As stride halves; 324 words, %32=4 -> ldsm conflict-free
#define SAW  324

#define AS_BYTES   (MT * SA * 2)               // 82944
#define ENC_OFF    AS_BYTES
#define PRED_OFF   (ENC_OFF + 8 * 64 * 4)      // +2048
#define JOINT_SMEM (PRED_OFF + 8 * 64 * 4)     // 87040

// Scratch
__device__ float  g_enc [B_ * T_ * DJ];
__device__ float  g_pred[B_ * U_ * DJ];
// W pre-shuffled into mma B-fragment order:
// uint4 index = (n16 * KSTEPS + kstep) * 32 + lane
__device__ __align__(16) __half g_wh[V_ * DJ];

// ---------------------------------------------------------------------------
__device__ __forceinline__ uint32_t smem_u32(const void* p) {
    return (uint32_t)__cvta_generic_to_shared(p);
}
__device__ __forceinline__ void ldsm_x4(uint32_t& r0, uint32_t& r1, uint32_t& r2,
                                        uint32_t& r3, uint32_t a) {
    asm volatile("ldmatrix.sync.aligned.m8n8.x4.shared.b16 {%0,%1,%2,%3}, [%4];\n"
                 : "=r"(r0), "=r"(r1), "=r"(r2), "=r"(r3) : "r"(a));
}
__device__ __forceinline__ float tanh_fast(float x) {
    float y;
    asm("tanh.approx.f32 %0, %1;" : "=f"(y) : "f"(x));
    return y;
}
__device__ __forceinline__ uint32_t packh2(float a, float b) {
    half2 h = __floats2half2_rn(a, b);
    return *(uint32_t*)&h;
}

// ---------------------------------------------------------------------------
// Merged prep kernel:
//   z=0: enc projection (32x64 fp32 tiles)
//   z=1: pred projection
//   z=2: W_out fp32 -> fp16 frag-shuffle (first 320 (y*10+x) slots)
// ---------------------------------------------------------------------------
__global__ __launch_bounds__(256)
void prep_kernel(const float* __restrict__ Aenc, const float* __restrict__ Wenc,
                 const float* __restrict__ benc, float* __restrict__ Cenc,
                 const float* __restrict__ Apred, const float* __restrict__ Wpred,
                 const float* __restrict__ bpred, float* __restrict__ Cpred,
                 const float* __restrict__ Wout, uint4* __restrict__ Wh) {
    int z = blockIdx.z;
    int tid = threadIdx.x;

    if (z == 2) {
        int blk = blockIdx.y * gridDim.x + blockIdx.x;
        if (blk >= 320) return;
        int gid = blk * 256 + tid;              // 0..81919
        int lane = gid & 31;
        int rest = gid >> 5;
        int ks = rest % KSTEPS;
        int n16 = rest / KSTEPS;
        int g = lane >> 2, tg = lane & 3;
        const float* r0p = Wout + (size_t)(n16 * 16 + g) * DJ + ks * 16 + tg * 2;
        const float* r1p = r0p + 8 * DJ;
        float2 w0 = *(const float2*)(r0p);
        float2 w1 = *(const float2*)(r0p + 8);
        float2 w2 = *(const float2*)(r1p);
        float2 w3 = *(const float2*)(r1p + 8);
        uint4 o;
        o.x = packh2(w0.x, w0.y);
        o.y = packh2(w1.x, w1.y);
        o.z = packh2(w2.x, w2.y);
        o.w = packh2(w3.x, w3.y);
        Wh[gid] = o;
        return;
    }

    const float* A    = z ? Apred : Aenc;
    const float* W    = z ? Wpred : Wenc;
    const float* bias = z ? bpred : benc;
    float*       C    = z ? Cpred : Cenc;
    int M = z ? (B_ * U_) : (B_ * T_);
    int D = z ? DP : DE;

    int m0 = blockIdx.y * 32;
    if (m0 >= M) return;
    int j0 = blockIdx.x * 64;

    __shared__ float As[32][17];
    __shared__ float Ws[64][17];
    int tx = tid & 15, ty = tid >> 4;

    float acc[2][4];
    #pragma unroll
    for (int i = 0; i < 2; i++)
        #pragma unroll
        for (int j = 0; j < 4; j++) acc[i][j] = 0.f;

    for (int kt = 0; kt < D; kt += 16) {
        #pragma unroll
        for (int i = 0; i < 2; i++) {
            int idx = tid + i * 256;
            int r = idx >> 4, k = idx & 15;
            int m = m0 + r;
            As[r][k] = (m < M) ? A[(size_t)m * D + kt + k] : 0.f;
        }
        #pragma unroll
        for (int i = 0; i < 4; i++) {
            int idx = tid + i * 256;
            int r = idx >> 4, k = idx & 15;
            Ws[r][k] = W[(size_t)(j0 + r) * D + kt + k];
        }
        __syncthreads();
        #pragma unroll
        for (int kk = 0; kk < 16; kk++) {
            float a0 = As[ty][kk], a1 = As[ty + 16][kk];
            float w[4];
            #pragma unroll
            for (int j = 0; j < 4; j++) w[j] = Ws[tx + j * 16][kk];
            #pragma unroll
            for (int j = 0; j < 4; j++) {
                acc[0][j] += a0 * w[j];
                acc[1][j] += a1 * w[j];
            }
        }
        __syncthreads();
    }
    #pragma unroll
    for (int i = 0; i < 2; i++) {
        int m = m0 + ty + i * 16;
        if (m >= M) continue;
        #pragma unroll
        for (int j = 0; j < 4; j++) {
            int jj = j0 + tx + j * 16;
            C[(size_t)m * DJ + jj] = acc[i][j] + bias[jj];
        }
    }
}

// ---------------------------------------------------------------------------
// Joint kernel: CTA = 64 M-rows (8t x 8u) x V=1024 in 4 passes of N=256.
// 256 threads = 8 warps (2m x 4n), warp tile 32x64, 2 CTAs/SM.
// Phase 2: no barriers, B streamed from L2 in frag order, A via ldsm.
// ---------------------------------------------------------------------------
extern __shared__ __align__(128) char dynsmem[];

__global__ __launch_bounds__(256, 2)
void joint_kernel(const float* __restrict__ bout, float* __restrict__ out) {
    half*  As    = (half*)dynsmem;
    float* encs  = (float*)(dynsmem + ENC_OFF);    // 8 x 64
    float* preds = (float*)(dynsmem + PRED_OFF);   // 8 x 64

    int tid = threadIdx.x;
    int wid = tid >> 5, lane = tid & 31;
    int g = lane >> 2, tg = lane & 3;
    int warp_m = wid >> 2, warp_n = wid & 3;   // 2 x 4

    int bx = blockIdx.x;               // 1400 CTAs: 25 t-tiles x 7 u-tiles x 8 b
    int b = bx / 175, r = bx % 175;
    int tt = r % 25, ut = r / 25;
    int t0 = tt * 8, u0 = ut * 8;

    uint32_t as_u = smem_u32(As);

    // ---- Phase 1: A = tanh(enc + pred), fp16, once ----
    const float* encp  = g_enc  + ((size_t)b * T_ + t0) * DJ;
    const float* predp = g_pred + ((size_t)b * U_ + u0) * DJ;
    for (int kc = 0; kc < DJ; kc += 64) {
        {   // enc 8x64 + pred 8x64: 256 float2 each, one of each per thread
            int rw = tid >> 5, kp = tid & 31;
            *(float2*)(encs + rw * 64 + kp * 2) =
                *(const float2*)(encp + (size_t)rw * DJ + kc + kp * 2);
            int u = u0 + rw;
            float2 pv = make_float2(0.f, 0.f);
            if (u < U_) pv = *(const float2*)(predp + (size_t)rw * DJ + kc + kp * 2);
            *(float2*)(preds + rw * 64 + kp * 2) = pv;
        }
        __syncthreads();
        #pragma unroll
        for (int i = 0; i < 8; i++) {      // 64 rows x 32 half2
            int idx = tid + i * 256;
            int row = idx >> 5, kp = idx & 31;   // row = t-local*8 + u-local
            float2 e = *(const float2*)(encs + ((row >> 3) << 6) + kp * 2);
            float2 p = *(const float2*)(preds + ((row & 7) << 6) + kp * 2);
            half2 h = __floats2half2_rn(tanh_fast(e.x + p.x), tanh_fast(e.y + p.y));
            *(half2*)(As + row * SA + kc + kp * 2) = h;
        }
        __syncthreads();
    }

    // ---- Phase 2: 4 vocab passes x 40 k16-steps. No barriers. ----
    int j = lane >> 3;
    int a_row = warp_m * 32 + (lane & 7) + (j & 1) * 8;   // + mt*16
    int a_col = (j >> 1) * 4;

    const uint4* wsh = (const uint4*)g_wh;

    for (int np = 0; np < NPASS; np++) {
        float acc[2][8][4];
        #pragma unroll
        for (int mt = 0; mt < 2; mt++)
            #pragma unroll
            for (int nt = 0; nt < 8; nt++)
                #pragma unroll
                for (int c = 0; c < 4; c++) acc[mt][nt][c] = 0.f;

        int n16b = np * (NTILE / 16) + warp_n * 4;
        const uint4* wp0 = wsh + ((size_t)(n16b + 0) * KSTEPS) * 32 + lane;
        const uint4* wp1 = wsh + ((size_t)(n16b + 1) * KSTEPS) * 32 + lane;
        const uint4* wp2 = wsh + ((size_t)(n16b + 2) * KSTEPS) * 32 + lane;
        const uint4* wp3 = wsh + ((size_t)(n16b + 3) * KSTEPS) * 32 + lane;

        for (int ks = 0; ks < KSTEPS; ks++) {
            uint4 bq[4];
            bq[0] = wp0[ks * 32];
            bq[1] = wp1[ks * 32];
            bq[2] = wp2[ks * 32];
            bq[3] = wp3[ks * 32];

            uint32_t a[2][4];
            #pragma unroll
            for (int mt = 0; mt < 2; mt++)
                ldsm_x4(a[mt][0], a[mt][1], a[mt][2], a[mt][3],
                        as_u + (uint32_t)((a_row + mt * 16) * SAW
                                          + ks * 8 + a_col) * 4);
            #pragma unroll
            for (int mt = 0; mt < 2; mt++) {
                #pragma unroll
                for (int nt = 0; nt < 8; nt++) {
                    uint32_t bf0 = (nt & 1) ? bq[nt >> 1].z : bq[nt >> 1].x;
                    uint32_t bf1 = (nt & 1) ? bq[nt >> 1].w : bq[nt >> 1].y;
                    asm volatile(
                        "mma.sync.aligned.m16n8k16.row.col.f32.f16.f16.f32 "
                        "{%0,%1,%2,%3}, {%4,%5,%6,%7}, {%8,%9}, {%0,%1,%2,%3};\n"
                        : "+f"(acc[mt][nt][0]), "+f"(acc[mt][nt][1]),
                          "+f"(acc[mt][nt][2]), "+f"(acc[mt][nt][3])
                        : "r"(a[mt][0]), "r"(a[mt][1]), "r"(a[mt][2]), "r"(a[mt][3]),
                          "r"(bf0), "r"(bf1));
                }
            }
        }

        // epilogue for this pass
        int n0 = np * NTILE;
        #pragma unroll
        for (int nt = 0; nt < 8; nt++) {
            int n = n0 + warp_n * 64 + nt * 8 + tg * 2;
            float bo0 = __ldg(bout + n);
            float bo1 = __ldg(bout + n + 1);
            #pragma unroll
            for (int mt = 0; mt < 2; mt++) {
                #pragma unroll
                for (int h = 0; h < 2; h++) {
                    int row = warp_m * 32 + mt * 16 + g + h * 8;
                    int t = t0 + (row >> 3), u = u0 + (row & 7);
                    if (u < U_) {
                        size_t base = ((((size_t)b * T_ + t) * U_ + u) * V_) + n;
                        float2 v = make_float2(acc[mt][nt][h * 2] + bo0,
                                               acc[mt][nt][h * 2 + 1] + bo1);
                        *(float2*)(out + base) = v;
                    }
                }
            }
        }
    }
}

// ---------------------------------------------------------------------------
extern "C" void kernel_launch(void* const* d_in, const int* in_sizes, int n_in,
                              void* d_out, int out_size) {
    const float* encoder_out   = (const float*)d_in[0];
    const float* predictor_out = (const float*)d_in[1];
    const float* W_enc  = (const float*)d_in[2];
    const float* b_enc  = (const float*)d_in[3];
    const float* W_pred = (const float*)d_in[4];
    const float* b_pred = (const float*)d_in[5];
    const float* W_out  = (const float*)d_in[6];
    const float* b_out  = (const float*)d_in[7];
    float* out = (float*)d_out;

    float* enc_buf;
    float* pred_buf;
    uint4* wh_buf;
    cudaGetSymbolAddress((void**)&enc_buf,  g_enc);
    cudaGetSymbolAddress((void**)&pred_buf, g_pred);
    cudaGetSymbolAddress((void**)&wh_buf,   g_wh);

    cudaFuncSetAttribute(joint_kernel,
                         cudaFuncAttributeMaxDynamicSharedMemorySize, JOINT_SMEM);

    {   // merged prep: z=0 enc proj, z=1 pred proj, z=2 W convert
        dim3 grid(DJ / 64, (B_ * T_ + 31) / 32, 3);
        prep_kernel<<<grid, 256>>>(encoder_out, W_enc, b_enc, enc_buf,
                                   predictor_out, W_pred, b_pred, pred_buf,
                                   W_out, wh_buf);
    }

    // joint: 25 t-tiles x 7 u-tiles x 8 b = 1400 CTAs, 2/SM
    joint_kernel<<<1400, 256, JOINT_SMEM>>>(b_out, out);
}